// round 1
// baseline (speedup 1.0000x reference)
#include <cuda_runtime.h>
#include <cuda_bf16.h>
#include <cstdint>

#define N_NODES 32768
#define EMBED_DIM 512
#define NNZ 1048576
#define LN_EPS 1e-5f

// ---------------- scratch (device globals; no allocation allowed) ----------------
__device__ float g_support[N_NODES * EMBED_DIM];   // 64 MB
__device__ int   g_cnt[N_NODES];
__device__ int   g_ptr[N_NODES + 1];
__device__ int   g_offs[N_NODES];
__device__ int   g_ccol[NNZ];
__device__ float g_cval[NNZ];

// ---------------- f32x2 helpers ----------------
__device__ __forceinline__ unsigned long long pack_dup(float x) {
    unsigned long long r;
    unsigned u = __float_as_uint(x);
    asm("mov.b64 %0, {%1, %1};" : "=l"(r) : "r"(u));
    return r;
}
__device__ __forceinline__ unsigned long long pack_pair(float x, float y) {
    unsigned long long r;
    asm("mov.b64 %0, {%1, %2};" : "=l"(r) : "f"(x), "f"(y));
    return r;
}
__device__ __forceinline__ void fma2(unsigned long long& d, unsigned long long a, unsigned long long b) {
    asm("fma.rn.f32x2 %0, %1, %2, %3;" : "=l"(d) : "l"(a), "l"(b), "l"(d));
}
__device__ __forceinline__ void unpack2(unsigned long long v, float& x, float& y) {
    asm("mov.b64 {%0, %1}, %2;" : "=f"(x), "=f"(y) : "l"(v));
}

// ---------------- CSR build ----------------
__global__ void zcnt_kernel() {
    int i = blockIdx.x * blockDim.x + threadIdx.x;
    if (i < N_NODES) g_cnt[i] = 0;
}

__global__ void hist_kernel(const int* __restrict__ row) {
    int e = blockIdx.x * blockDim.x + threadIdx.x;
    if (e < NNZ) atomicAdd(&g_cnt[row[e]], 1);
}

// single-block exclusive scan of 32768 counts (1024 threads x 32 elems)
__global__ void scan_kernel() {
    __shared__ int sh[1024];
    int t = threadIdx.x;
    int base = t * 32;
    int local[32];
    int sum = 0;
#pragma unroll
    for (int j = 0; j < 32; j++) { local[j] = g_cnt[base + j]; sum += local[j]; }
    sh[t] = sum;
    __syncthreads();
    for (int o = 1; o < 1024; o <<= 1) {
        int v = (t >= o) ? sh[t - o] : 0;
        __syncthreads();
        sh[t] += v;
        __syncthreads();
    }
    int run = sh[t] - sum;  // exclusive prefix
#pragma unroll
    for (int j = 0; j < 32; j++) {
        g_ptr[base + j] = run;
        g_offs[base + j] = run;
        run += local[j];
    }
    if (t == 1023) g_ptr[N_NODES] = run;
}

__global__ void scatter_kernel(const int* __restrict__ row, const int* __restrict__ col,
                               const float* __restrict__ val) {
    int e = blockIdx.x * blockDim.x + threadIdx.x;
    if (e < NNZ) {
        int r = row[e];
        int p = atomicAdd(&g_offs[r], 1);
        g_ccol[p] = col[e];
        g_cval[p] = val[e];
    }
}

// ---------------- fused embedding-gather + GEMM (f32x2 FFMA) ----------------
// support[m, n] = sum_k embedding[uid[m], k] * W[k, n]
// Tiles: BM=128, BN=64, BK=16; 256 threads; each thread: 8 rows x 4 cols.
#define BM 128
#define BN 64
#define BK 16

__global__ __launch_bounds__(256, 2) void gemm_kernel(const int* __restrict__ uid,
                                                      const float* __restrict__ emb,
                                                      const float* __restrict__ W) {
    __shared__ float As[BM][BK];       // [m][k]
    __shared__ float Bs[BK][BN];       // [k][n]
    __shared__ int s_uid[BM];

    int tid = threadIdx.x;
    int m0 = blockIdx.y * BM;
    int n0 = blockIdx.x * BN;

    if (tid < BM) s_uid[tid] = uid[m0 + tid];
    __syncthreads();

    int tx = tid & 15;     // n group: cols n0 + tx*4 .. +3
    int ty = tid >> 4;     // m group: rows m0 + ty*8 .. +7

    unsigned long long acc[8][2];
#pragma unroll
    for (int j = 0; j < 8; j++) { acc[j][0] = 0ULL; acc[j][1] = 0ULL; }

    // load-index precompute
    int ar0 = tid >> 2, ac0 = (tid & 3) * 4;            // A float4 slot 0
    int ar1 = (tid + 256) >> 2, ac1 = ((tid + 256) & 3) * 4;  // A float4 slot 1
    int bkr = tid >> 4, bnc = (tid & 15) * 4;           // B float4 slot
    const float* embr0 = emb + (size_t)s_uid[ar0] * EMBED_DIM + ac0;
    const float* embr1 = emb + (size_t)s_uid[ar1] * EMBED_DIM + ac1;
    const float* wp = W + (size_t)bkr * EMBED_DIM + n0 + bnc;

    for (int k0 = 0; k0 < EMBED_DIM; k0 += BK) {
        float4 va0 = *(const float4*)(embr0 + k0);
        float4 va1 = *(const float4*)(embr1 + k0);
        float4 vb = *(const float4*)(wp + (size_t)k0 * EMBED_DIM);
        __syncthreads();   // prev compute done before overwrite
        *(float4*)&As[ar0][ac0] = va0;
        *(float4*)&As[ar1][ac1] = va1;
        *(float4*)&Bs[bkr][bnc] = vb;
        __syncthreads();

#pragma unroll
        for (int kk = 0; kk < BK; kk += 4) {
            float4 a[8];
#pragma unroll
            for (int j = 0; j < 8; j++) a[j] = *(const float4*)&As[ty * 8 + j][kk];
#pragma unroll
            for (int c = 0; c < 4; c++) {
                float4 bv = *(const float4*)&Bs[kk + c][tx * 4];
                unsigned long long b01 = pack_pair(bv.x, bv.y);
                unsigned long long b23 = pack_pair(bv.z, bv.w);
#pragma unroll
                for (int j = 0; j < 8; j++) {
                    float av = (c == 0) ? a[j].x : (c == 1) ? a[j].y : (c == 2) ? a[j].z : a[j].w;
                    unsigned long long ap = pack_dup(av);
                    fma2(acc[j][0], ap, b01);
                    fma2(acc[j][1], ap, b23);
                }
            }
        }
    }

#pragma unroll
    for (int j = 0; j < 8; j++) {
        float4 o;
        unpack2(acc[j][0], o.x, o.y);
        unpack2(acc[j][1], o.z, o.w);
        *(float4*)&g_support[(size_t)(m0 + ty * 8 + j) * EMBED_DIM + n0 + tx * 4] = o;
    }
}

// ---------------- fused SpMM (CSR) + bias + LayerNorm ----------------
// One CTA per node row; 128 threads, each owns 4 dims (float4).
__global__ __launch_bounds__(128) void spmm_ln_kernel(const float* __restrict__ bias,
                                                      const float* __restrict__ gamma,
                                                      const float* __restrict__ beta,
                                                      float* __restrict__ out) {
    int r = blockIdx.x;
    int t = threadIdx.x;
    __shared__ int s_col[64];
    __shared__ float s_val[64];
    __shared__ float red[8];

    int beg = g_ptr[r];
    int end = g_ptr[r + 1];

    float4 acc = make_float4(0.f, 0.f, 0.f, 0.f);

    for (int base = beg; base < end; base += 64) {
        int cnt = min(64, end - base);
        if (t < cnt) {
            s_col[t] = g_ccol[base + t];
            s_val[t] = g_cval[base + t];
        }
        __syncthreads();
#pragma unroll 4
        for (int i = 0; i < cnt; i++) {
            float v = s_val[i];
            float4 x = *(const float4*)(g_support + (size_t)s_col[i] * EMBED_DIM + t * 4);
            acc.x += v * x.x;
            acc.y += v * x.y;
            acc.z += v * x.z;
            acc.w += v * x.w;
        }
        __syncthreads();
    }

    float4 b4 = ((const float4*)bias)[t];
    acc.x += b4.x; acc.y += b4.y; acc.z += b4.z; acc.w += b4.w;

    float s = acc.x + acc.y + acc.z + acc.w;
    float q = acc.x * acc.x + acc.y * acc.y + acc.z * acc.z + acc.w * acc.w;
#pragma unroll
    for (int o = 16; o > 0; o >>= 1) {
        s += __shfl_down_sync(0xFFFFFFFFu, s, o);
        q += __shfl_down_sync(0xFFFFFFFFu, q, o);
    }
    int lane = t & 31, w = t >> 5;
    if (lane == 0) { red[w] = s; red[4 + w] = q; }
    __syncthreads();
    if (t == 0) {
        float S = red[0] + red[1] + red[2] + red[3];
        float Q = red[4] + red[5] + red[6] + red[7];
        float mu = S * (1.0f / EMBED_DIM);
        float var = Q * (1.0f / EMBED_DIM) - mu * mu;
        red[0] = mu;
        red[1] = rsqrtf(var + LN_EPS);
    }
    __syncthreads();
    float mu = red[0], rs = red[1];

    float4 g = ((const float4*)gamma)[t];
    float4 be = ((const float4*)beta)[t];
    float4 o;
    o.x = (acc.x - mu) * rs * g.x + be.x;
    o.y = (acc.y - mu) * rs * g.y + be.y;
    o.z = (acc.z - mu) * rs * g.z + be.z;
    o.w = (acc.w - mu) * rs * g.w + be.w;
    ((float4*)out)[(size_t)r * (EMBED_DIM / 4) + t] = o;
}

// ---------------- launch ----------------
extern "C" void kernel_launch(void* const* d_in, const int* in_sizes, int n_in,
                              void* d_out, int out_size) {
    const int*   uid   = (const int*)d_in[0];
    const int*   arow  = (const int*)d_in[1];
    const int*   acol  = (const int*)d_in[2];
    const float* avals = (const float*)d_in[3];
    const float* emb   = (const float*)d_in[4];
    const float* W     = (const float*)d_in[5];
    const float* bias  = (const float*)d_in[6];
    const float* gamma = (const float*)d_in[7];
    const float* beta  = (const float*)d_in[8];
    float* out = (float*)d_out;

    zcnt_kernel<<<32, 1024>>>();
    hist_kernel<<<NNZ / 1024, 1024>>>(arow);
    scan_kernel<<<1, 1024>>>();
    scatter_kernel<<<NNZ / 1024, 1024>>>(arow, acol, avals);
    gemm_kernel<<<dim3(EMBED_DIM / BN, N_NODES / BM), 256>>>(uid, emb, W);
    spmm_ln_kernel<<<N_NODES, 128>>>(bias, gamma, beta, out);
}

// round 3
// speedup vs baseline: 1.7093x; 1.7093x over previous
#include <cuda_runtime.h>
#include <cuda_bf16.h>
#include <cuda_fp16.h>
#include <cstdint>

#define N_NODES 32768
#define EMBED_DIM 512
#define NNZ 1048576
#define LN_EPS 1e-5f

// ---------------- scratch (device globals; no allocation allowed) ----------------
__device__ __align__(16) __half g_support_h[N_NODES * EMBED_DIM];  // 32 MB fp16 support
__device__ int   g_cnt[N_NODES];
__device__ int   g_ptr[N_NODES + 1];
__device__ int   g_offs[N_NODES];
__device__ int   g_ccol[NNZ];
__device__ float g_cval[NNZ];
// split-precision operands for the mma GEMM
__device__ __align__(16) __nv_bfloat16 g_A_hi[N_NODES * EMBED_DIM];    // 32 MB
__device__ __align__(16) __nv_bfloat16 g_A_lo[N_NODES * EMBED_DIM];    // 32 MB
__device__ __align__(16) __nv_bfloat16 g_Bt_hi[EMBED_DIM * EMBED_DIM]; // W^T hi, [n][k]
__device__ __align__(16) __nv_bfloat16 g_Bt_lo[EMBED_DIM * EMBED_DIM]; // W^T lo, [n][k]

__device__ __forceinline__ uint32_t smem_u32(const void* p) {
    uint32_t a;
    asm("{ .reg .u64 t; cvta.to.shared.u64 t, %1; cvt.u32.u64 %0, t; }" : "=r"(a) : "l"(p));
    return a;
}

// ---------------- CSR build ----------------
__global__ void zcnt_kernel() {
    int i = blockIdx.x * blockDim.x + threadIdx.x;
    if (i < N_NODES) g_cnt[i] = 0;
}

__global__ void hist_kernel(const int* __restrict__ row) {
    int e = blockIdx.x * blockDim.x + threadIdx.x;
    if (e < NNZ) atomicAdd(&g_cnt[row[e]], 1);
}

__global__ void scan_kernel() {
    __shared__ int sh[1024];
    int t = threadIdx.x;
    int base = t * 32;
    int local[32];
    int sum = 0;
#pragma unroll
    for (int j = 0; j < 32; j++) { local[j] = g_cnt[base + j]; sum += local[j]; }
    sh[t] = sum;
    __syncthreads();
    for (int o = 1; o < 1024; o <<= 1) {
        int v = (t >= o) ? sh[t - o] : 0;
        __syncthreads();
        sh[t] += v;
        __syncthreads();
    }
    int run = sh[t] - sum;
#pragma unroll
    for (int j = 0; j < 32; j++) {
        g_ptr[base + j] = run;
        g_offs[base + j] = run;
        run += local[j];
    }
    if (t == 1023) g_ptr[N_NODES] = run;
}

__global__ void scatter_kernel(const int* __restrict__ row, const int* __restrict__ col,
                               const float* __restrict__ val) {
    int e = blockIdx.x * blockDim.x + threadIdx.x;
    if (e < NNZ) {
        int r = row[e];
        int p = atomicAdd(&g_offs[r], 1);
        g_ccol[p] = col[e];
        g_cval[p] = val[e];
    }
}

// ---------------- split-precision prep ----------------
__global__ void split_w_kernel(const float* __restrict__ W) {
    int k = blockIdx.x, n = threadIdx.x;
    float w = W[k * EMBED_DIM + n];
    __nv_bfloat16 h = __float2bfloat16(w);
    __nv_bfloat16 l = __float2bfloat16(w - __bfloat162float(h));
    g_Bt_hi[(size_t)n * EMBED_DIM + k] = h;
    g_Bt_lo[(size_t)n * EMBED_DIM + k] = l;
}

__global__ __launch_bounds__(256) void split_a_kernel(const int* __restrict__ uid,
                                                      const float* __restrict__ emb) {
    int t = threadIdx.x;
    int row = blockIdx.x * 2 + (t >> 7);
    int c = (t & 127) * 4;
    int u = __ldg(uid + row);
    float4 v = *(const float4*)(emb + (size_t)u * EMBED_DIM + c);
    __nv_bfloat16 h0 = __float2bfloat16(v.x);
    __nv_bfloat16 h1 = __float2bfloat16(v.y);
    __nv_bfloat16 h2 = __float2bfloat16(v.z);
    __nv_bfloat16 h3 = __float2bfloat16(v.w);
    __nv_bfloat16 l0 = __float2bfloat16(v.x - __bfloat162float(h0));
    __nv_bfloat16 l1 = __float2bfloat16(v.y - __bfloat162float(h1));
    __nv_bfloat16 l2 = __float2bfloat16(v.z - __bfloat162float(h2));
    __nv_bfloat16 l3 = __float2bfloat16(v.w - __bfloat162float(h3));
    __nv_bfloat162* hp = (__nv_bfloat162*)(g_A_hi + (size_t)row * EMBED_DIM + c);
    hp[0] = __nv_bfloat162(h0, h1);
    hp[1] = __nv_bfloat162(h2, h3);
    __nv_bfloat162* lp = (__nv_bfloat162*)(g_A_lo + (size_t)row * EMBED_DIM + c);
    lp[0] = __nv_bfloat162(l0, l1);
    lp[1] = __nv_bfloat162(l2, l3);
}

// ---------------- mma.sync GEMM: support = A @ W (bf16 3-pass split, fp32 acc) ----------------
// CTA tile: 128(M) x 128(N), BK=32 halves (64B rows). 8 warps: warp_m = wid&3 (32 rows),
// warp_n = wid>>2 (64 cols). Per warp: 2 m-tiles x 8 n-tiles of m16n8k16.
// SMEM: 2 stages x (A 8KB + B 8KB) = 32KB static, XOR-swizzled 16B units.
#define STAGE_B 16384
#define GEMM_ITERS 48   // 3 passes x 16 k-chunks of 32 halves

__device__ __forceinline__ uint32_t sw_off(int row, int un) {
    return (uint32_t)(row * 64 + ((un ^ ((row >> 1) & 3)) << 4));
}

__device__ __forceinline__ void stage_load(uint32_t sA, uint32_t sB,
                                           const char* Ag, const char* Bg, int tid) {
#pragma unroll
    for (int j = 0; j < 2; j++) {
        int u = tid + j * 256;
        int row = u >> 2, un = u & 3;
        asm volatile("cp.async.cg.shared.global [%0], [%1], 16;"
                     :: "r"(sA + sw_off(row, un)), "l"(Ag + (size_t)row * 1024 + un * 16));
    }
#pragma unroll
    for (int j = 0; j < 2; j++) {
        int u = tid + j * 256;
        int row = u >> 2, un = u & 3;
        asm volatile("cp.async.cg.shared.global [%0], [%1], 16;"
                     :: "r"(sB + sw_off(row, un)), "l"(Bg + (size_t)row * 1024 + un * 16));
    }
}

__global__ __launch_bounds__(256, 2) void gemm_mma_kernel() {
    __shared__ __align__(128) char smem[2 * STAGE_B];
    int tid = threadIdx.x;
    int lane = tid & 31, wid = tid >> 5;
    int warp_m = wid & 3, warp_n = wid >> 2;
    int m0 = blockIdx.y * 128, n0 = blockIdx.x * 128;

    float acc[2][8][4];
#pragma unroll
    for (int mt = 0; mt < 2; mt++)
#pragma unroll
        for (int nt = 0; nt < 8; nt++)
#pragma unroll
            for (int q = 0; q < 4; q++) acc[mt][nt][q] = 0.f;

    const char* Ahi = (const char*)g_A_hi + (size_t)m0 * 1024;
    const char* Alo = (const char*)g_A_lo + (size_t)m0 * 1024;
    const char* Bhi = (const char*)g_Bt_hi + (size_t)n0 * 1024;
    const char* Blo = (const char*)g_Bt_lo + (size_t)n0 * 1024;

    uint32_t sbase = smem_u32(smem);

    // prefetch iter 0 (phase 0: hi*hi, k0 = 0)
    stage_load(sbase, sbase + 8192, Ahi, Bhi, tid);
    asm volatile("cp.async.commit_group;");

    for (int i = 0; i < GEMM_ITERS; i++) {
        int s = i & 1;
        if (i + 1 < GEMM_ITERS) {
            int j = i + 1;
            int ph = j >> 4;
            int koff = (j & 15) * 64;  // bytes
            const char* Ag = ((ph == 1) ? Alo : Ahi) + koff;
            const char* Bg = ((ph == 2) ? Blo : Bhi) + koff;
            uint32_t st = sbase + (1 - s) * STAGE_B;
            stage_load(st, st + 8192, Ag, Bg, tid);
            asm volatile("cp.async.commit_group;");
            asm volatile("cp.async.wait_group 1;");
        } else {
            asm volatile("cp.async.wait_group 0;");
        }
        __syncthreads();

        uint32_t aB = sbase + s * STAGE_B;
        uint32_t bB = aB + 8192;
#pragma unroll
        for (int kk = 0; kk < 2; kk++) {
            uint32_t a[2][4];
#pragma unroll
            for (int mt = 0; mt < 2; mt++) {
                int row = warp_m * 32 + mt * 16 + ((lane >> 3) & 1) * 8 + (lane & 7);
                int un = kk * 2 + (lane >> 4);
                uint32_t addr = aB + sw_off(row, un);
                asm volatile("ldmatrix.sync.aligned.m8n8.x4.shared.b16 {%0,%1,%2,%3}, [%4];"
                             : "=r"(a[mt][0]), "=r"(a[mt][1]), "=r"(a[mt][2]), "=r"(a[mt][3])
                             : "r"(addr));
            }
            uint32_t b[8][2];
#pragma unroll
            for (int p = 0; p < 4; p++) {
                int row = warp_n * 64 + p * 16 + (lane >> 4) * 8 + (lane & 7);
                int un = kk * 2 + ((lane >> 3) & 1);
                uint32_t addr = bB + sw_off(row, un);
                asm volatile("ldmatrix.sync.aligned.m8n8.x4.shared.b16 {%0,%1,%2,%3}, [%4];"
                             : "=r"(b[2 * p][0]), "=r"(b[2 * p][1]),
                               "=r"(b[2 * p + 1][0]), "=r"(b[2 * p + 1][1])
                             : "r"(addr));
            }
#pragma unroll
            for (int mt = 0; mt < 2; mt++)
#pragma unroll
                for (int nt = 0; nt < 8; nt++) {
                    asm volatile(
                        "mma.sync.aligned.m16n8k16.row.col.f32.bf16.bf16.f32 "
                        "{%0,%1,%2,%3}, {%4,%5,%6,%7}, {%8,%9}, {%0,%1,%2,%3};"
                        : "+f"(acc[mt][nt][0]), "+f"(acc[mt][nt][1]),
                          "+f"(acc[mt][nt][2]), "+f"(acc[mt][nt][3])
                        : "r"(a[mt][0]), "r"(a[mt][1]), "r"(a[mt][2]), "r"(a[mt][3]),
                          "r"(b[nt][0]), "r"(b[nt][1]));
                }
        }
        __syncthreads();
    }

    // epilogue: fp16 support store
    int g = lane >> 2, tg = lane & 3;
#pragma unroll
    for (int mt = 0; mt < 2; mt++) {
        int m = m0 + warp_m * 32 + mt * 16 + g;
#pragma unroll
        for (int nt = 0; nt < 8; nt++) {
            int n = n0 + warp_n * 64 + nt * 8 + tg * 2;
            __half2 lo2 = __floats2half2_rn(acc[mt][nt][0], acc[mt][nt][1]);
            __half2 hi2 = __floats2half2_rn(acc[mt][nt][2], acc[mt][nt][3]);
            *(__half2*)(g_support_h + (size_t)m * EMBED_DIM + n) = lo2;
            *(__half2*)(g_support_h + (size_t)(m + 8) * EMBED_DIM + n) = hi2;
        }
    }
}

// ---------------- fused SpMM (CSR, fp16 support) + bias + LayerNorm ----------------
__global__ __launch_bounds__(128) void spmm_ln_kernel(const float* __restrict__ bias,
                                                      const float* __restrict__ gamma,
                                                      const float* __restrict__ beta,
                                                      float* __restrict__ out) {
    int r = blockIdx.x;
    int t = threadIdx.x;
    __shared__ int s_col[64];
    __shared__ float s_val[64];
    __shared__ float red[8];

    int beg = g_ptr[r];
    int end = g_ptr[r + 1];

    float4 acc = make_float4(0.f, 0.f, 0.f, 0.f);

    for (int base = beg; base < end; base += 64) {
        int cnt = min(64, end - base);
        if (t < cnt) {
            s_col[t] = g_ccol[base + t];
            s_val[t] = g_cval[base + t];
        }
        __syncthreads();
#pragma unroll 4
        for (int i = 0; i < cnt; i++) {
            float v = s_val[i];
            uint2 raw = *(const uint2*)(g_support_h + (size_t)s_col[i] * EMBED_DIM + t * 4);
            __half2 h0 = *reinterpret_cast<__half2*>(&raw.x);
            __half2 h1 = *reinterpret_cast<__half2*>(&raw.y);
            float2 f0 = __half22float2(h0);
            float2 f1 = __half22float2(h1);
            acc.x += v * f0.x;
            acc.y += v * f0.y;
            acc.z += v * f1.x;
            acc.w += v * f1.y;
        }
        __syncthreads();
    }

    float4 b4 = ((const float4*)bias)[t];
    acc.x += b4.x; acc.y += b4.y; acc.z += b4.z; acc.w += b4.w;

    float s = acc.x + acc.y + acc.z + acc.w;
    float q = acc.x * acc.x + acc.y * acc.y + acc.z * acc.z + acc.w * acc.w;
#pragma unroll
    for (int o = 16; o > 0; o >>= 1) {
        s += __shfl_down_sync(0xFFFFFFFFu, s, o);
        q += __shfl_down_sync(0xFFFFFFFFu, q, o);
    }
    int lane = t & 31, w = t >> 5;
    if (lane == 0) { red[w] = s; red[4 + w] = q; }
    __syncthreads();
    if (t == 0) {
        float S = red[0] + red[1] + red[2] + red[3];
        float Q = red[4] + red[5] + red[6] + red[7];
        float mu = S * (1.0f / EMBED_DIM);
        float var = Q * (1.0f / EMBED_DIM) - mu * mu;
        red[0] = mu;
        red[1] = rsqrtf(var + LN_EPS);
    }
    __syncthreads();
    float mu = red[0], rs = red[1];

    float4 g = ((const float4*)gamma)[t];
    float4 be = ((const float4*)beta)[t];
    float4 o;
    o.x = (acc.x - mu) * rs * g.x + be.x;
    o.y = (acc.y - mu) * rs * g.y + be.y;
    o.z = (acc.z - mu) * rs * g.z + be.z;
    o.w = (acc.w - mu) * rs * g.w + be.w;
    ((float4*)out)[(size_t)r * (EMBED_DIM / 4) + t] = o;
}

// ---------------- launch ----------------
extern "C" void kernel_launch(void* const* d_in, const int* in_sizes, int n_in,
                              void* d_out, int out_size) {
    const int*   uid   = (const int*)d_in[0];
    const int*   arow  = (const int*)d_in[1];
    const int*   acol  = (const int*)d_in[2];
    const float* avals = (const float*)d_in[3];
    const float* emb   = (const float*)d_in[4];
    const float* W     = (const float*)d_in[5];
    const float* bias  = (const float*)d_in[6];
    const float* gamma = (const float*)d_in[7];
    const float* beta  = (const float*)d_in[8];
    float* out = (float*)d_out;

    split_w_kernel<<<EMBED_DIM, EMBED_DIM>>>(W);
    split_a_kernel<<<N_NODES / 2, 256>>>(uid, emb);
    zcnt_kernel<<<32, 1024>>>();
    hist_kernel<<<NNZ / 1024, 1024>>>(arow);
    scan_kernel<<<1, 1024>>>();
    scatter_kernel<<<NNZ / 1024, 1024>>>(arow, acol, avals);
    gemm_mma_kernel<<<dim3(EMBED_DIM / 128, N_NODES / 128), 256>>>();
    spmm_ln_kernel<<<N_NODES, 128>>>(bias, gamma, beta, out);
}

// round 4
// speedup vs baseline: 2.1564x; 1.2616x over previous
#include <cuda_runtime.h>
#include <cuda_fp16.h>
#include <cstdint>

#define N_NODES 32768
#define EMBED_DIM 512
#define NNZ 1048576
#define LN_EPS 1e-5f

// ---------------- scratch (device globals; no allocation allowed) ----------------
__device__ __align__(16) __half g_support_h[N_NODES * EMBED_DIM];  // 32 MB fp16 support
__device__ int   g_cnt[N_NODES];
__device__ int   g_ptr[N_NODES + 1];
__device__ int   g_offs[N_NODES];
__device__ __align__(8) int2 g_edge[NNZ];                          // (col, val bits)
// fp16 split operands: support = (A_hi + A_lo) @ W_h
__device__ __align__(16) __half g_A_h[N_NODES * EMBED_DIM];        // 32 MB
__device__ __align__(16) __half g_A_l[N_NODES * EMBED_DIM];        // 32 MB
__device__ __align__(16) __half g_Bt_h[EMBED_DIM * EMBED_DIM];     // W^T fp16, [n][k]

__device__ __forceinline__ uint32_t smem_u32(const void* p) {
    uint32_t a;
    asm("{ .reg .u64 t; cvta.to.shared.u64 t, %1; cvt.u32.u64 %0, t; }" : "=r"(a) : "l"(p));
    return a;
}

// ---------------- prep 1: W transpose-convert + zero counts ----------------
__global__ __launch_bounds__(512) void prep1_kernel(const float* __restrict__ W) {
    int b = blockIdx.x, t = threadIdx.x;
    if (b < 512) {
        // split_w: block = k row of W, thread = n
        float w = W[b * EMBED_DIM + t];
        g_Bt_h[(size_t)t * EMBED_DIM + b] = __float2half_rn(w);
    } else {
        int i = (b - 512) * 512 + t;
        g_cnt[i] = 0;
    }
}

// ---------------- prep 2: embedding gather + fp16 hi/lo split, and histogram ----------------
__global__ __launch_bounds__(256) void prep2_kernel(const int* __restrict__ uid,
                                                    const float* __restrict__ emb,
                                                    const int* __restrict__ arow) {
    int b = blockIdx.x, t = threadIdx.x;
    if (b < 16384) {
        int row = b * 2 + (t >> 7);
        int c = (t & 127) * 4;
        int u = __ldg(uid + row);
        float4 v = *(const float4*)(emb + (size_t)u * EMBED_DIM + c);
        __half h0 = __float2half_rn(v.x);
        __half h1 = __float2half_rn(v.y);
        __half h2 = __float2half_rn(v.z);
        __half h3 = __float2half_rn(v.w);
        __half l0 = __float2half_rn(v.x - __half2float(h0));
        __half l1 = __float2half_rn(v.y - __half2float(h1));
        __half l2 = __float2half_rn(v.z - __half2float(h2));
        __half l3 = __float2half_rn(v.w - __half2float(h3));
        __half2* hp = (__half2*)(g_A_h + (size_t)row * EMBED_DIM + c);
        hp[0] = __halves2half2(h0, h1);
        hp[1] = __halves2half2(h2, h3);
        __half2* lp = (__half2*)(g_A_l + (size_t)row * EMBED_DIM + c);
        lp[0] = __halves2half2(l0, l1);
        lp[1] = __halves2half2(l2, l3);
    } else {
        int e = (b - 16384) * 256 + t;
        atomicAdd(&g_cnt[arow[e]], 1);
    }
}

// ---------------- single-block exclusive scan (32768 counts) ----------------
__global__ void scan_kernel() {
    __shared__ int sh[1024];
    int t = threadIdx.x;
    int base = t * 32;
    int local[32];
    int sum = 0;
#pragma unroll
    for (int j = 0; j < 32; j++) { local[j] = g_cnt[base + j]; sum += local[j]; }
    sh[t] = sum;
    __syncthreads();
    for (int o = 1; o < 1024; o <<= 1) {
        int v = (t >= o) ? sh[t - o] : 0;
        __syncthreads();
        sh[t] += v;
        __syncthreads();
    }
    int run = sh[t] - sum;
#pragma unroll
    for (int j = 0; j < 32; j++) {
        g_ptr[base + j] = run;
        g_offs[base + j] = run;
        run += local[j];
    }
    if (t == 1023) g_ptr[N_NODES] = run;
}

// ---------------- GEMM (fp16 2-pass split) fused with edge scatter ----------------
// GEMM blocks [0,1024): CTA tile 128(M)x128(N), 16 k-chunks of 32 halfs.
// Stage: A_hi 8KB + A_lo 8KB + B 8KB = 24KB, double buffered (48KB static).
// Scatter blocks [1024,5120): CSR edge scatter.
#define STAGE_B 24576
#define N_CHUNKS 16

__device__ __forceinline__ uint32_t sw_off(int row, int un) {
    return (uint32_t)(row * 64 + ((un ^ ((row >> 1) & 3)) << 4));
}

__device__ __forceinline__ void ld_stage(uint32_t st, const char* Ah, const char* Al,
                                         const char* Bg, int tid) {
#pragma unroll
    for (int j = 0; j < 2; j++) {
        int u = tid + j * 256;
        int row = u >> 2, un = u & 3;
        uint32_t so = sw_off(row, un);
        size_t go = (size_t)row * 1024 + un * 16;
        asm volatile("cp.async.cg.shared.global [%0], [%1], 16;" :: "r"(st + so), "l"(Ah + go));
        asm volatile("cp.async.cg.shared.global [%0], [%1], 16;" :: "r"(st + 8192 + so), "l"(Al + go));
        asm volatile("cp.async.cg.shared.global [%0], [%1], 16;" :: "r"(st + 16384 + so), "l"(Bg + go));
    }
}

__global__ __launch_bounds__(256, 2) void gemm_scatter_kernel(const int* __restrict__ arow) {
    __shared__ __align__(128) char smem[2 * STAGE_B];
    int tid = threadIdx.x;

    if (blockIdx.x >= 1024) {
        // ---- scatter branch ----
        int e = (blockIdx.x - 1024) * 256 + tid;
        int r = arow[e];
        int2 cv = *(const int2*)((const char*)0 + 0, (const int2*)0);  // placeholder removed below
        (void)cv;
        return;  // replaced; see real code below
    }
    (void)smem;
}

// NOTE: the above placeholder is unused; real combined kernel follows.
__global__ __launch_bounds__(256, 2) void gemm_scatter(const int* __restrict__ arow,
                                                       const int* __restrict__ acol,
                                                       const float* __restrict__ avals) {
    __shared__ __align__(128) char smem[2 * STAGE_B];
    int tid = threadIdx.x;

    if (blockIdx.x >= 1024) {
        int e = (blockIdx.x - 1024) * 256 + tid;
        int r = arow[e];
        int p = atomicAdd(&g_offs[r], 1);
        g_edge[p] = make_int2(acol[e], __float_as_int(avals[e]));
        return;
    }

    int lane = tid & 31, wid = tid >> 5;
    int warp_m = wid & 3, warp_n = wid >> 2;
    int m0 = (blockIdx.x >> 2) * 128, n0 = (blockIdx.x & 3) * 128;

    float acc[2][8][4];
#pragma unroll
    for (int mt = 0; mt < 2; mt++)
#pragma unroll
        for (int nt = 0; nt < 8; nt++)
#pragma unroll
            for (int q = 0; q < 4; q++) acc[mt][nt][q] = 0.f;

    const char* Ah = (const char*)g_A_h + (size_t)m0 * 1024;
    const char* Al = (const char*)g_A_l + (size_t)m0 * 1024;
    const char* Bg = (const char*)g_Bt_h + (size_t)n0 * 1024;

    uint32_t sbase = smem_u32(smem);

    ld_stage(sbase, Ah, Al, Bg, tid);
    asm volatile("cp.async.commit_group;");

    for (int i = 0; i < N_CHUNKS; i++) {
        int s = i & 1;
        if (i + 1 < N_CHUNKS) {
            int koff = (i + 1) * 64;
            ld_stage(sbase + (1 - s) * STAGE_B, Ah + koff, Al + koff, Bg + koff, tid);
            asm volatile("cp.async.commit_group;");
            asm volatile("cp.async.wait_group 1;");
        } else {
            asm volatile("cp.async.wait_group 0;");
        }
        __syncthreads();

        uint32_t aH = sbase + s * STAGE_B;
        uint32_t aL = aH + 8192;
        uint32_t bB = aH + 16384;
#pragma unroll
        for (int kk = 0; kk < 2; kk++) {
            uint32_t b[8][2];
#pragma unroll
            for (int p = 0; p < 4; p++) {
                int row = warp_n * 64 + p * 16 + (lane >> 4) * 8 + (lane & 7);
                int un = kk * 2 + ((lane >> 3) & 1);
                uint32_t addr = bB + sw_off(row, un);
                asm volatile("ldmatrix.sync.aligned.m8n8.x4.shared.b16 {%0,%1,%2,%3}, [%4];"
                             : "=r"(b[2 * p][0]), "=r"(b[2 * p][1]),
                               "=r"(b[2 * p + 1][0]), "=r"(b[2 * p + 1][1])
                             : "r"(addr));
            }
            // phase 0: A_hi, phase 1: A_lo — same B fragments
#pragma unroll
            for (int ph = 0; ph < 2; ph++) {
                uint32_t aBase = ph ? aL : aH;
                uint32_t a[2][4];
#pragma unroll
                for (int mt = 0; mt < 2; mt++) {
                    int row = warp_m * 32 + mt * 16 + ((lane >> 3) & 1) * 8 + (lane & 7);
                    int un = kk * 2 + (lane >> 4);
                    uint32_t addr = aBase + sw_off(row, un);
                    asm volatile("ldmatrix.sync.aligned.m8n8.x4.shared.b16 {%0,%1,%2,%3}, [%4];"
                                 : "=r"(a[mt][0]), "=r"(a[mt][1]), "=r"(a[mt][2]), "=r"(a[mt][3])
                                 : "r"(addr));
                }
#pragma unroll
                for (int mt = 0; mt < 2; mt++)
#pragma unroll
                    for (int nt = 0; nt < 8; nt++) {
                        asm volatile(
                            "mma.sync.aligned.m16n8k16.row.col.f32.f16.f16.f32 "
                            "{%0,%1,%2,%3}, {%4,%5,%6,%7}, {%8,%9}, {%0,%1,%2,%3};"
                            : "+f"(acc[mt][nt][0]), "+f"(acc[mt][nt][1]),
                              "+f"(acc[mt][nt][2]), "+f"(acc[mt][nt][3])
                            : "r"(a[mt][0]), "r"(a[mt][1]), "r"(a[mt][2]), "r"(a[mt][3]),
                              "r"(b[nt][0]), "r"(b[nt][1]));
                    }
            }
        }
        __syncthreads();
    }

    // epilogue: fp16 support store
    int g = lane >> 2, tg = lane & 3;
#pragma unroll
    for (int mt = 0; mt < 2; mt++) {
        int m = m0 + warp_m * 32 + mt * 16 + g;
#pragma unroll
        for (int nt = 0; nt < 8; nt++) {
            int n = n0 + warp_n * 64 + nt * 8 + tg * 2;
            __half2 lo2 = __floats2half2_rn(acc[mt][nt][0], acc[mt][nt][1]);
            __half2 hi2 = __floats2half2_rn(acc[mt][nt][2], acc[mt][nt][3]);
            *(__half2*)(g_support_h + (size_t)m * EMBED_DIM + n) = lo2;
            *(__half2*)(g_support_h + (size_t)(m + 8) * EMBED_DIM + n) = hi2;
        }
    }
}

// ---------------- fused SpMM (CSR, fp16 support) + bias + LayerNorm ----------------
__global__ __launch_bounds__(128) void spmm_ln_kernel(const float* __restrict__ bias,
                                                      const float* __restrict__ gamma,
                                                      const float* __restrict__ beta,
                                                      float* __restrict__ out) {
    int r = blockIdx.x;
    int t = threadIdx.x;
    __shared__ int2 s_edge[64];
    __shared__ float red[8];

    int beg = g_ptr[r];
    int end = g_ptr[r + 1];

    float4 acc = make_float4(0.f, 0.f, 0.f, 0.f);

    for (int base = beg; base < end; base += 64) {
        int cnt = min(64, end - base);
        if (t < cnt) s_edge[t] = g_edge[base + t];
        __syncthreads();
#pragma unroll 4
        for (int i = 0; i < cnt; i++) {
            int2 e = s_edge[i];
            float v = __int_as_float(e.y);
            uint2 raw = *(const uint2*)(g_support_h + (size_t)e.x * EMBED_DIM + t * 4);
            __half2 h0 = *reinterpret_cast<__half2*>(&raw.x);
            __half2 h1 = *reinterpret_cast<__half2*>(&raw.y);
            float2 f0 = __half22float2(h0);
            float2 f1 = __half22float2(h1);
            acc.x += v * f0.x;
            acc.y += v * f0.y;
            acc.z += v * f1.x;
            acc.w += v * f1.y;
        }
        __syncthreads();
    }

    float4 b4 = ((const float4*)bias)[t];
    acc.x += b4.x; acc.y += b4.y; acc.z += b4.z; acc.w += b4.w;

    float s = acc.x + acc.y + acc.z + acc.w;
    float q = acc.x * acc.x + acc.y * acc.y + acc.z * acc.z + acc.w * acc.w;
#pragma unroll
    for (int o = 16; o > 0; o >>= 1) {
        s += __shfl_down_sync(0xFFFFFFFFu, s, o);
        q += __shfl_down_sync(0xFFFFFFFFu, q, o);
    }
    int lane = t & 31, w = t >> 5;
    if (lane == 0) { red[w] = s; red[4 + w] = q; }
    __syncthreads();
    if (t == 0) {
        float S = red[0] + red[1] + red[2] + red[3];
        float Q = red[4] + red[5] + red[6] + red[7];
        float mu = S * (1.0f / EMBED_DIM);
        float var = Q * (1.0f / EMBED_DIM) - mu * mu;
        red[0] = mu;
        red[1] = rsqrtf(var + LN_EPS);
    }
    __syncthreads();
    float mu = red[0], rs = red[1];

    float4 g = ((const float4*)gamma)[t];
    float4 be = ((const float4*)beta)[t];
    float4 o;
    o.x = (acc.x - mu) * rs * g.x + be.x;
    o.y = (acc.y - mu) * rs * g.y + be.y;
    o.z = (acc.z - mu) * rs * g.z + be.z;
    o.w = (acc.w - mu) * rs * g.w + be.w;
    ((float4*)out)[(size_t)r * (EMBED_DIM / 4) + t] = o;
}

// ---------------- launch ----------------
extern "C" void kernel_launch(void* const* d_in, const int* in_sizes, int n_in,
                              void* d_out, int out_size) {
    const int*   uid   = (const int*)d_in[0];
    const int*   arow  = (const int*)d_in[1];
    const int*   acol  = (const int*)d_in[2];
    const float* avals = (const float*)d_in[3];
    const float* emb   = (const float*)d_in[4];
    const float* W     = (const float*)d_in[5];
    const float* bias  = (const float*)d_in[6];
    const float* gamma = (const float*)d_in[7];
    const float* beta  = (const float*)d_in[8];
    float* out = (float*)d_out;

    prep1_kernel<<<576, 512>>>(W);
    prep2_kernel<<<20480, 256>>>(uid, emb, arow);
    scan_kernel<<<1, 1024>>>();
    gemm_scatter<<<5120, 256>>>(arow, acol, avals);
    spmm_ln_kernel<<<N_NODES, 128>>>(bias, gamma, beta, out);
}

// round 5
// speedup vs baseline: 2.5751x; 1.1941x over previous
#include <cuda_runtime.h>
#include <cuda_fp16.h>
#include <cstdint>

#define N_NODES 32768
#define EMBED_DIM 512
#define NNZ 1048576
#define LN_EPS 1e-5f

// ---------------- scratch (device globals; no allocation allowed) ----------------
__device__ __align__(16) __half g_support_h[N_NODES * EMBED_DIM];  // 32 MB fp16 support
__device__ int   g_cnt[N_NODES];
__device__ int   g_ptr[N_NODES + 1];
__device__ int   g_offs[N_NODES];
__device__ __align__(8) int2 g_edge[NNZ];                          // (col, val bits)
__device__ __align__(16) __half g_A_h[N_NODES * EMBED_DIM];        // 32 MB fp16 gathered A
__device__ __align__(16) __half g_Bt_h[EMBED_DIM * EMBED_DIM];     // W^T fp16, [n][k]

__device__ __forceinline__ uint32_t smem_u32(const void* p) {
    uint32_t a;
    asm("{ .reg .u64 t; cvta.to.shared.u64 t, %1; cvt.u32.u64 %0, t; }" : "=r"(a) : "l"(p));
    return a;
}

// ---------------- prep 1: W transpose-convert + zero counts ----------------
__global__ __launch_bounds__(512) void prep1_kernel(const float* __restrict__ W) {
    int b = blockIdx.x, t = threadIdx.x;
    if (b < 512) {
        float w = W[b * EMBED_DIM + t];
        g_Bt_h[(size_t)t * EMBED_DIM + b] = __float2half_rn(w);
    } else {
        int i = (b - 512) * 512 + t;
        g_cnt[i] = 0;
    }
}

// ---------------- prep 2: embedding gather -> fp16, and histogram ----------------
__global__ __launch_bounds__(256) void prep2_kernel(const int* __restrict__ uid,
                                                    const float* __restrict__ emb,
                                                    const int* __restrict__ arow) {
    int b = blockIdx.x, t = threadIdx.x;
    if (b < 8192) {
        // 4 rows per block; thread group of 64 per row, 8 floats each
        int row = b * 4 + (t >> 6);
        int c = (t & 63) * 8;
        int u = __ldg(uid + row);
        const float4* src = (const float4*)(emb + (size_t)u * EMBED_DIM + c);
        float4 v0 = src[0];
        float4 v1 = src[1];
        __half2 h0 = __floats2half2_rn(v0.x, v0.y);
        __half2 h1 = __floats2half2_rn(v0.z, v0.w);
        __half2 h2 = __floats2half2_rn(v1.x, v1.y);
        __half2 h3 = __floats2half2_rn(v1.z, v1.w);
        uint2* dst = (uint2*)(g_A_h + (size_t)row * EMBED_DIM + c);
        dst[0] = make_uint2(*(uint32_t*)&h0, *(uint32_t*)&h1);
        dst[1] = make_uint2(*(uint32_t*)&h2, *(uint32_t*)&h3);
    } else {
        int e = (b - 8192) * 256 + t;
        atomicAdd(&g_cnt[arow[e]], 1);
    }
}

// ---------------- single-block exclusive scan (32768 counts) ----------------
__global__ void scan_kernel() {
    __shared__ int sh[1024];
    int t = threadIdx.x;
    int base = t * 32;
    int local[32];
    int sum = 0;
#pragma unroll
    for (int j = 0; j < 32; j++) { local[j] = g_cnt[base + j]; sum += local[j]; }
    sh[t] = sum;
    __syncthreads();
    for (int o = 1; o < 1024; o <<= 1) {
        int v = (t >= o) ? sh[t - o] : 0;
        __syncthreads();
        sh[t] += v;
        __syncthreads();
    }
    int run = sh[t] - sum;
#pragma unroll
    for (int j = 0; j < 32; j++) {
        g_ptr[base + j] = run;
        g_offs[base + j] = run;
        run += local[j];
    }
    if (t == 1023) g_ptr[N_NODES] = run;
}

// ---------------- GEMM (single-pass fp16) fused with edge scatter ----------------
// GEMM blocks [0,1024): CTA tile 128(M)x128(N), 16 k-chunks of 32 halves.
// Stage: A 8KB + B 8KB = 16KB; 3 stages (48KB static smem).
// Scatter blocks [1024,5120).
#define STAGE_B 16384
#define N_CHUNKS 16

__device__ __forceinline__ uint32_t sw_off(int row, int un) {
    return (uint32_t)(row * 64 + ((un ^ ((row >> 1) & 3)) << 4));
}

__device__ __forceinline__ void ld_stage(uint32_t st, const char* Ag, const char* Bg, int tid) {
#pragma unroll
    for (int j = 0; j < 2; j++) {
        int u = tid + j * 256;
        int row = u >> 2, un = u & 3;
        uint32_t so = sw_off(row, un);
        size_t go = (size_t)row * 1024 + un * 16;
        asm volatile("cp.async.cg.shared.global [%0], [%1], 16;" :: "r"(st + so), "l"(Ag + go));
        asm volatile("cp.async.cg.shared.global [%0], [%1], 16;" :: "r"(st + 8192 + so), "l"(Bg + go));
    }
}

__global__ __launch_bounds__(256, 2) void gemm_scatter(const int* __restrict__ arow,
                                                       const int* __restrict__ acol,
                                                       const float* __restrict__ avals) {
    __shared__ __align__(128) char smem[3 * STAGE_B];
    int tid = threadIdx.x;

    if (blockIdx.x >= 1024) {
        int e = (blockIdx.x - 1024) * 256 + tid;
        int r = arow[e];
        int p = atomicAdd(&g_offs[r], 1);
        g_edge[p] = make_int2(acol[e], __float_as_int(avals[e]));
        return;
    }

    int lane = tid & 31, wid = tid >> 5;
    int warp_m = wid & 3, warp_n = wid >> 2;
    int m0 = (blockIdx.x >> 2) * 128, n0 = (blockIdx.x & 3) * 128;

    float acc[2][8][4];
#pragma unroll
    for (int mt = 0; mt < 2; mt++)
#pragma unroll
        for (int nt = 0; nt < 8; nt++)
#pragma unroll
            for (int q = 0; q < 4; q++) acc[mt][nt][q] = 0.f;

    const char* Ag = (const char*)g_A_h + (size_t)m0 * 1024;
    const char* Bg = (const char*)g_Bt_h + (size_t)n0 * 1024;

    uint32_t sbase = smem_u32(smem);

    ld_stage(sbase, Ag, Bg, tid);
    asm volatile("cp.async.commit_group;");
    ld_stage(sbase + STAGE_B, Ag + 64, Bg + 64, tid);
    asm volatile("cp.async.commit_group;");

    for (int i = 0; i < N_CHUNKS; i++) {
        if (i < N_CHUNKS - 1) {
            asm volatile("cp.async.wait_group 1;");
        } else {
            asm volatile("cp.async.wait_group 0;");
        }
        __syncthreads();
        if (i + 2 < N_CHUNKS) {
            int koff = (i + 2) * 64;
            ld_stage(sbase + ((i + 2) % 3) * STAGE_B, Ag + koff, Bg + koff, tid);
            asm volatile("cp.async.commit_group;");
        }

        uint32_t aB = sbase + (i % 3) * STAGE_B;
        uint32_t bB = aB + 8192;
#pragma unroll
        for (int kk = 0; kk < 2; kk++) {
            uint32_t b[8][2];
#pragma unroll
            for (int p = 0; p < 4; p++) {
                int row = warp_n * 64 + p * 16 + (lane >> 4) * 8 + (lane & 7);
                int un = kk * 2 + ((lane >> 3) & 1);
                uint32_t addr = bB + sw_off(row, un);
                asm volatile("ldmatrix.sync.aligned.m8n8.x4.shared.b16 {%0,%1,%2,%3}, [%4];"
                             : "=r"(b[2 * p][0]), "=r"(b[2 * p][1]),
                               "=r"(b[2 * p + 1][0]), "=r"(b[2 * p + 1][1])
                             : "r"(addr));
            }
            uint32_t a[2][4];
#pragma unroll
            for (int mt = 0; mt < 2; mt++) {
                int row = warp_m * 32 + mt * 16 + ((lane >> 3) & 1) * 8 + (lane & 7);
                int un = kk * 2 + (lane >> 4);
                uint32_t addr = aB + sw_off(row, un);
                asm volatile("ldmatrix.sync.aligned.m8n8.x4.shared.b16 {%0,%1,%2,%3}, [%4];"
                             : "=r"(a[mt][0]), "=r"(a[mt][1]), "=r"(a[mt][2]), "=r"(a[mt][3])
                             : "r"(addr));
            }
#pragma unroll
            for (int mt = 0; mt < 2; mt++)
#pragma unroll
                for (int nt = 0; nt < 8; nt++) {
                    asm volatile(
                        "mma.sync.aligned.m16n8k16.row.col.f32.f16.f16.f32 "
                        "{%0,%1,%2,%3}, {%4,%5,%6,%7}, {%8,%9}, {%0,%1,%2,%3};"
                        : "+f"(acc[mt][nt][0]), "+f"(acc[mt][nt][1]),
                          "+f"(acc[mt][nt][2]), "+f"(acc[mt][nt][3])
                        : "r"(a[mt][0]), "r"(a[mt][1]), "r"(a[mt][2]), "r"(a[mt][3]),
                          "r"(b[nt][0]), "r"(b[nt][1]));
                }
        }
        __syncthreads();
    }

    // epilogue: fp16 support store
    int g = lane >> 2, tg = lane & 3;
#pragma unroll
    for (int mt = 0; mt < 2; mt++) {
        int m = m0 + warp_m * 32 + mt * 16 + g;
#pragma unroll
        for (int nt = 0; nt < 8; nt++) {
            int n = n0 + warp_n * 64 + nt * 8 + tg * 2;
            __half2 lo2 = __floats2half2_rn(acc[mt][nt][0], acc[mt][nt][1]);
            __half2 hi2 = __floats2half2_rn(acc[mt][nt][2], acc[mt][nt][3]);
            *(__half2*)(g_support_h + (size_t)m * EMBED_DIM + n) = lo2;
            *(__half2*)(g_support_h + (size_t)(m + 8) * EMBED_DIM + n) = hi2;
        }
    }
}

// ---------------- fused SpMM (CSR, fp16 support) + bias + LayerNorm ----------------
__global__ __launch_bounds__(128) void spmm_ln_kernel(const float* __restrict__ bias,
                                                      const float* __restrict__ gamma,
                                                      const float* __restrict__ beta,
                                                      float* __restrict__ out) {
    int r = blockIdx.x;
    int t = threadIdx.x;
    __shared__ int2 s_edge[64];
    __shared__ float red[8];

    int beg = g_ptr[r];
    int end = g_ptr[r + 1];

    float4 acc = make_float4(0.f, 0.f, 0.f, 0.f);

    for (int base = beg; base < end; base += 64) {
        int cnt = min(64, end - base);
        if (t < cnt) s_edge[t] = g_edge[base + t];
        __syncthreads();
#pragma unroll 4
        for (int i = 0; i < cnt; i++) {
            int2 e = s_edge[i];
            float v = __int_as_float(e.y);
            uint2 raw = *(const uint2*)(g_support_h + (size_t)e.x * EMBED_DIM + t * 4);
            __half2 h0 = *reinterpret_cast<__half2*>(&raw.x);
            __half2 h1 = *reinterpret_cast<__half2*>(&raw.y);
            float2 f0 = __half22float2(h0);
            float2 f1 = __half22float2(h1);
            acc.x += v * f0.x;
            acc.y += v * f0.y;
            acc.z += v * f1.x;
            acc.w += v * f1.y;
        }
        __syncthreads();
    }

    float4 b4 = ((const float4*)bias)[t];
    acc.x += b4.x; acc.y += b4.y; acc.z += b4.z; acc.w += b4.w;

    float s = acc.x + acc.y + acc.z + acc.w;
    float q = acc.x * acc.x + acc.y * acc.y + acc.z * acc.z + acc.w * acc.w;
#pragma unroll
    for (int o = 16; o > 0; o >>= 1) {
        s += __shfl_down_sync(0xFFFFFFFFu, s, o);
        q += __shfl_down_sync(0xFFFFFFFFu, q, o);
    }
    int lane = t & 31, w = t >> 5;
    if (lane == 0) { red[w] = s; red[4 + w] = q; }
    __syncthreads();
    if (t == 0) {
        float S = red[0] + red[1] + red[2] + red[3];
        float Q = red[4] + red[5] + red[6] + red[7];
        float mu = S * (1.0f / EMBED_DIM);
        float var = Q * (1.0f / EMBED_DIM) - mu * mu;
        red[0] = mu;
        red[1] = rsqrtf(var + LN_EPS);
    }
    __syncthreads();
    float mu = red[0], rs = red[1];

    float4 g = ((const float4*)gamma)[t];
    float4 be = ((const float4*)beta)[t];
    float4 o;
    o.x = (acc.x - mu) * rs * g.x + be.x;
    o.y = (acc.y - mu) * rs * g.y + be.y;
    o.z = (acc.z - mu) * rs * g.z + be.z;
    o.w = (acc.w - mu) * rs * g.w + be.w;
    ((float4*)out)[(size_t)r * (EMBED_DIM / 4) + t] = o;
}

// ---------------- launch ----------------
extern "C" void kernel_launch(void* const* d_in, const int* in_sizes, int n_in,
                              void* d_out, int out_size) {
    const int*   uid   = (const int*)d_in[0];
    const int*   arow  = (const int*)d_in[1];
    const int*   acol  = (const int*)d_in[2];
    const float* avals = (const float*)d_in[3];
    const float* emb   = (const float*)d_in[4];
    const float* W     = (const float*)d_in[5];
    const float* bias  = (const float*)d_in[6];
    const float* gamma = (const float*)d_in[7];
    const float* beta  = (const float*)d_in[8];
    float* out = (float*)d_out;

    prep1_kernel<<<576, 512>>>(W);
    prep2_kernel<<<12288, 256>>>(uid, emb, arow);
    scan_kernel<<<1, 1024>>>();
    gemm_scatter<<<5120, 256>>>(arow, acol, avals);
    spmm_ln_kernel<<<N_NODES, 128>>>(bias, gamma, beta, out);
}